// round 15
// baseline (speedup 1.0000x reference)
// R15 = R14 resubmission (R14 failed on broker infra, no kernel signal).
#include <cuda_runtime.h>
#include <cuda_fp16.h>
#include <cstdint>

// Problem constants (shapes fixed by the reference)
#define MAXN    100000
#define MAXE    3400000
#define INF     128
#define HID     64
// padded CSR capacity: E + 16*N pad + prefetch slack
#define MAXCV   (MAXE + 16 * MAXN + 256)

// Scratch (device globals per allocation rules)
__device__ __half g_hA[(size_t)MAXN * HID];    // feature table A (12.8 MB)
__device__ __half g_hB[(size_t)MAXN * HID];    // feature table B (12.8 MB)
__device__ __half g_w1t[64 * 128];             // W1^T (n-major) fp16
__device__ __half g_w2t[64 * 64];              // W2^T (n-major) fp16
__device__ int   g_deg[MAXN];                  // reset by scatter each replay
__device__ int   g_rptr[MAXN + 1];             // padded CSR offsets
__device__ int   g_pos[MAXE];                  // per-edge within-row position
__device__ int2  g_cv[MAXCV];                  // (col, val-bits); pads = (0,0)
__device__ int   g_flag[128];                  // lookback flags (0/1/2)
__device__ int   g_agg[128];
__device__ int   g_pref[128];

__device__ __forceinline__ uint32_t pack_h2(float a, float b) {
    __half2 h = __floats2half2_rn(a, b);
    return *reinterpret_cast<uint32_t*>(&h);
}

// m16n8k16 fp16 MMA, fp32 accum, in-place C
__device__ __forceinline__ void mma16816(float* c,
    uint32_t a0, uint32_t a1, uint32_t a2, uint32_t a3,
    uint32_t b0, uint32_t b1)
{
    asm volatile(
        "mma.sync.aligned.m16n8k16.row.col.f32.f16.f16.f32 "
        "{%0,%1,%2,%3}, {%4,%5,%6,%7}, {%8,%9}, {%0,%1,%2,%3};\n"
        : "+f"(c[0]), "+f"(c[1]), "+f"(c[2]), "+f"(c[3])
        : "r"(a0), "r"(a1), "r"(a2), "r"(a3), "r"(b0), "r"(b1));
}

// ---------------------------------------------------------------------------
// Weight transpose + fp16 convert: Wt[n][k] = W[k][n]   (champion config)
// ---------------------------------------------------------------------------
__global__ void wconv_kernel(const float* __restrict__ W1,
                             const float* __restrict__ W2,
                             __half* __restrict__ Wt1, __half* __restrict__ Wt2)
{
    int i = blockIdx.x * blockDim.x + threadIdx.x;
    if (i < 64 * 128) {
        int nn = i >> 7, k = i & 127;
        Wt1[i] = __float2half(W1[k * 64 + nn]);
    }
    int j = i - 64 * 128;
    if (j >= 0 && j < 64 * 64) {
        int nn = j >> 6, k = j & 63;
        Wt2[j] = __float2half(W2[k * 64 + nn]);
    }
}

// ---------------------------------------------------------------------------
// Build: hist (atomic returns = within-row position, ILP4) ->
//        scan (padded degrees + inline pad-zero, decoupled lookback) ->
//        atomic-free scatter (R12-measured 42.3us)
// ---------------------------------------------------------------------------
__global__ void hist_kernel(const int* __restrict__ erow, int* __restrict__ deg,
                            int* __restrict__ pos, int E)
{
    int t = blockIdx.x * blockDim.x + threadIdx.x;
    int stride4 = gridDim.x * blockDim.x * 4;
    for (int i = t * 4; i + 4 <= E; i += stride4) {
        int4 r = __ldg(reinterpret_cast<const int4*>(erow + i));
        int p0 = atomicAdd(deg + r.x, 1);
        int p1 = atomicAdd(deg + r.y, 1);
        int p2 = atomicAdd(deg + r.z, 1);
        int p3 = atomicAdd(deg + r.w, 1);
        *reinterpret_cast<int4*>(pos + i) = make_int4(p0, p1, p2, p3);
    }
    if (t == 0)
        for (int j = E & ~3; j < E; j++)
            pos[j] = atomicAdd(deg + __ldg(erow + j), 1);
}

// Exclusive scan of PADDED degrees ((deg+15)&~15), decoupled lookback.
// Zeroes each row's padding slots [excl+deg, excl+pad) and the 64-slot tail
// slack — disjoint from scatter's edge slots, so no sync needed between
// scan and scatter beyond stream ordering.
__global__ __launch_bounds__(256) void scan_kernel(
    const int* __restrict__ deg, int* __restrict__ rptr,
    int2* __restrict__ cv, int n, int nb)
{
    __shared__ int sh[256];
    __shared__ int sh_base;
    const int tid = threadIdx.x;
    const int bid = blockIdx.x;

    int base = bid * 1024 + tid * 4;
    int raw[4], v[4]; int s4 = 0;
    #pragma unroll
    for (int j = 0; j < 4; j++) {
        raw[j] = (base + j < n) ? deg[base + j] : 0;
        v[j]   = (raw[j] + 15) & ~15;
        s4 += v[j];
    }
    sh[tid] = s4; __syncthreads();
    #pragma unroll
    for (int off = 1; off < 256; off <<= 1) {
        int y = (tid >= off) ? sh[tid - off] : 0;
        __syncthreads();
        sh[tid] += y;
        __syncthreads();
    }
    int total = sh[255];

    if (tid == 0) {
        int b;
        if (bid == 0) {
            g_pref[0] = total;
            __threadfence();
            atomicExch(&g_flag[0], 2);
            b = 0;
        } else {
            g_agg[bid] = total;
            __threadfence();
            atomicExch(&g_flag[bid], 1);
            int sum = 0;
            for (int j = bid - 1; ; ) {
                int f;
                do { f = atomicAdd(&g_flag[j], 0); } while (f == 0);
                if (f == 2) { sum += atomicAdd(&g_pref[j], 0); break; }
                sum += atomicAdd(&g_agg[j], 0);
                j--;
            }
            g_pref[bid] = sum + total;
            __threadfence();
            atomicExch(&g_flag[bid], 2);
            b = sum;
        }
        sh_base = b;
        if (bid == nb - 1) {
            int end = b + total;
            rptr[n] = end;
            int2 z = make_int2(0, 0);
            for (int k = 0; k < 64; k++) cv[end + k] = z;   // prefetch slack
        }
    }
    __syncthreads();

    int excl = sh[tid] - s4 + sh_base;
    int2 z = make_int2(0, 0);
    #pragma unroll
    for (int j = 0; j < 4; j++) {
        if (base + j < n) {
            rptr[base + j] = excl;
            for (int p = excl + raw[j]; p < excl + v[j]; p++) cv[p] = z;
        }
        excl += v[j];
    }
}

// Atomic-free placement: cv[rptr[r] + pos[i]] = (col, val). 4-edge ILP.
// Resets deg/flags for the next graph replay.
__global__ void scatter_kernel(
    const int* __restrict__ erow, const int* __restrict__ ecol,
    const float* __restrict__ eval, const int* __restrict__ pos,
    const int* __restrict__ rptr, int2* __restrict__ cv,
    int* __restrict__ deg, int n, int E)
{
    int t = blockIdx.x * blockDim.x + threadIdx.x;
    int stride = gridDim.x * blockDim.x;
    int stride4 = stride * 4;
    for (int i = t * 4; i + 4 <= E; i += stride4) {
        int4   r = __ldg(reinterpret_cast<const int4*>(erow + i));
        int4   c = __ldg(reinterpret_cast<const int4*>(ecol + i));
        float4 v = __ldg(reinterpret_cast<const float4*>(eval + i));
        int4   p = __ldg(reinterpret_cast<const int4*>(pos + i));
        int b0 = __ldg(rptr + r.x);
        int b1 = __ldg(rptr + r.y);
        int b2 = __ldg(rptr + r.z);
        int b3 = __ldg(rptr + r.w);
        cv[b0 + p.x] = make_int2(c.x, __float_as_int(v.x));
        cv[b1 + p.y] = make_int2(c.y, __float_as_int(v.y));
        cv[b2 + p.z] = make_int2(c.z, __float_as_int(v.z));
        cv[b3 + p.w] = make_int2(c.w, __float_as_int(v.w));
    }
    if (t == 0) {
        for (int j = E & ~3; j < E; j++) {
            int r = __ldg(erow + j);
            cv[__ldg(rptr + r) + pos[j]] =
                make_int2(__ldg(ecol + j), __float_as_int(__ldg(eval + j)));
        }
    }
    for (int i = t; i < n; i += stride) deg[i] = 0;
    if (t < 128) g_flag[t] = 0;
}

// ---------------------------------------------------------------------------
// GEMM1 (tensor core, champion): H[n,64] fp16 = X[n,128] fp32 @ W1[128,64]
// ---------------------------------------------------------------------------
#define XS1 136
__global__ __launch_bounds__(256) void gemm_in_tc(
    const float* __restrict__ X, const __half* __restrict__ Wt,
    __half* __restrict__ H, int n)
{
    extern __shared__ __half sm1[];
    __half* xs = sm1;               // [128][136]
    __half* ws = sm1 + 128 * XS1;   // [64][136]

    const int tid  = threadIdx.x;
    const int row0 = blockIdx.x * 128;

    for (int idx = tid; idx < 64 * 16; idx += 256) {
        int r = idx >> 4, c = idx & 15;
        uint4 v = *reinterpret_cast<const uint4*>(Wt + r * 128 + c * 8);
        *reinterpret_cast<uint4*>(ws + r * XS1 + c * 8) = v;
    }
    for (int idx = tid; idx < 128 * 16; idx += 256) {
        int r = idx >> 4, c = idx & 15;
        int gr = row0 + r;
        uint4 o = make_uint4(0u, 0u, 0u, 0u);
        if (gr < n) {
            const float4* p = reinterpret_cast<const float4*>(X + (size_t)gr * INF + c * 8);
            float4 f0 = __ldg(p);
            float4 f1 = __ldg(p + 1);
            o.x = pack_h2(f0.x, f0.y); o.y = pack_h2(f0.z, f0.w);
            o.z = pack_h2(f1.x, f1.y); o.w = pack_h2(f1.z, f1.w);
        }
        *reinterpret_cast<uint4*>(xs + r * XS1 + c * 8) = o;
    }
    __syncthreads();

    const int warp = tid >> 5, lane = tid & 31;
    const int g = lane >> 2, tg = lane & 3;
    const int m0 = warp * 16;

    float acc[8][4];
    #pragma unroll
    for (int i = 0; i < 8; i++)
        #pragma unroll
        for (int j = 0; j < 4; j++) acc[i][j] = 0.f;

    const __half* xb = xs + (m0 + g) * XS1 + 2 * tg;
    const __half* wb = ws + g * XS1 + 2 * tg;

    #pragma unroll
    for (int kb = 0; kb < 128; kb += 16) {
        uint32_t a0 = *reinterpret_cast<const uint32_t*>(xb + kb);
        uint32_t a1 = *reinterpret_cast<const uint32_t*>(xb + kb + 8 * XS1);
        uint32_t a2 = *reinterpret_cast<const uint32_t*>(xb + kb + 8);
        uint32_t a3 = *reinterpret_cast<const uint32_t*>(xb + kb + 8 * XS1 + 8);
        #pragma unroll
        for (int nf = 0; nf < 8; nf++) {
            uint32_t b0 = *reinterpret_cast<const uint32_t*>(wb + nf * 8 * XS1 + kb);
            uint32_t b1 = *reinterpret_cast<const uint32_t*>(wb + nf * 8 * XS1 + kb + 8);
            mma16816(acc[nf], a0, a1, a2, a3, b0, b1);
        }
    }

    const int r1 = row0 + m0 + g, r2 = r1 + 8;
    #pragma unroll
    for (int nf = 0; nf < 8; nf++) {
        int col = nf * 8 + 2 * tg;
        if (r1 < n)
            *reinterpret_cast<uint32_t*>(H + (size_t)r1 * HID + col) = pack_h2(acc[nf][0], acc[nf][1]);
        if (r2 < n)
            *reinterpret_cast<uint32_t*>(H + (size_t)r2 * HID + col) = pack_h2(acc[nf][2], acc[nf][3]);
    }
}

// ---------------------------------------------------------------------------
// GEMM2 (tensor core, champion): H2[n,64] fp16 = H1[n,64] fp16 @ W2[64,64]
// ---------------------------------------------------------------------------
#define XS2 72
__global__ __launch_bounds__(256) void gemm_hid_tc(
    const __half* __restrict__ Hin, const __half* __restrict__ Wt,
    __half* __restrict__ Hout, int n)
{
    __shared__ __half xs[128 * XS2];
    __shared__ __half ws[64 * XS2];

    const int tid  = threadIdx.x;
    const int row0 = blockIdx.x * 128;

    for (int idx = tid; idx < 64 * 8; idx += 256) {
        int r = idx >> 3, c = idx & 7;
        uint4 v = *reinterpret_cast<const uint4*>(Wt + r * 64 + c * 8);
        *reinterpret_cast<uint4*>(ws + r * XS2 + c * 8) = v;
    }
    for (int idx = tid; idx < 128 * 8; idx += 256) {
        int r = idx >> 3, c = idx & 7;
        int gr = row0 + r;
        uint4 v = make_uint4(0u, 0u, 0u, 0u);
        if (gr < n)
            v = __ldg(reinterpret_cast<const uint4*>(Hin + (size_t)gr * HID + c * 8));
        *reinterpret_cast<uint4*>(xs + r * XS2 + c * 8) = v;
    }
    __syncthreads();

    const int warp = tid >> 5, lane = tid & 31;
    const int g = lane >> 2, tg = lane & 3;
    const int m0 = warp * 16;

    float acc[8][4];
    #pragma unroll
    for (int i = 0; i < 8; i++)
        #pragma unroll
        for (int j = 0; j < 4; j++) acc[i][j] = 0.f;

    const __half* xb = xs + (m0 + g) * XS2 + 2 * tg;
    const __half* wb = ws + g * XS2 + 2 * tg;

    #pragma unroll
    for (int kb = 0; kb < 64; kb += 16) {
        uint32_t a0 = *reinterpret_cast<const uint32_t*>(xb + kb);
        uint32_t a1 = *reinterpret_cast<const uint32_t*>(xb + kb + 8 * XS2);
        uint32_t a2 = *reinterpret_cast<const uint32_t*>(xb + kb + 8);
        uint32_t a3 = *reinterpret_cast<const uint32_t*>(xb + kb + 8 * XS2 + 8);
        #pragma unroll
        for (int nf = 0; nf < 8; nf++) {
            uint32_t b0 = *reinterpret_cast<const uint32_t*>(wb + nf * 8 * XS2 + kb);
            uint32_t b1 = *reinterpret_cast<const uint32_t*>(wb + nf * 8 * XS2 + kb + 8);
            mma16816(acc[nf], a0, a1, a2, a3, b0, b1);
        }
    }

    const int r1 = row0 + m0 + g, r2 = r1 + 8;
    #pragma unroll
    for (int nf = 0; nf < 8; nf++) {
        int col = nf * 8 + 2 * tg;
        if (r1 < n)
            *reinterpret_cast<uint32_t*>(Hout + (size_t)r1 * HID + col) = pack_h2(acc[nf][0], acc[nf][1]);
        if (r2 < n)
            *reinterpret_cast<uint32_t*>(Hout + (size_t)r2 * HID + col) = pack_h2(acc[nf][2], acc[nf][3]);
    }
}

// ---------------------------------------------------------------------------
// SpMM core v4 (R7-measured ~55us): warp per dest row; rows padded to
// multiple of 16 with zero-weight entries -> NO predication. 16 edges per
// superstep, software-pipelined cv prefetch (overrun covered by next-row
// entries / zeroed slack; values discarded or weight-0).
// ---------------------------------------------------------------------------
#define ACC8(rr, ww)                                                           \
    { float2 f;                                                                \
      f = __half22float2(*reinterpret_cast<__half2*>(&rr.x));                  \
      a0.x = fmaf(ww, f.x, a0.x); a0.y = fmaf(ww, f.y, a0.y);                  \
      f = __half22float2(*reinterpret_cast<__half2*>(&rr.y));                  \
      a1.x = fmaf(ww, f.x, a1.x); a1.y = fmaf(ww, f.y, a1.y);                  \
      f = __half22float2(*reinterpret_cast<__half2*>(&rr.z));                  \
      a2.x = fmaf(ww, f.x, a2.x); a2.y = fmaf(ww, f.y, a2.y);                  \
      f = __half22float2(*reinterpret_cast<__half2*>(&rr.w));                  \
      a3.x = fmaf(ww, f.x, a3.x); a3.y = fmaf(ww, f.y, a3.y); }

#define SPMM_BODY                                                              \
    const int g = lane >> 3;                                                   \
    const int q = lane & 7;                                                    \
    const int s = __ldg(rptr + row);                                           \
    const int e = __ldg(rptr + row + 1);                                       \
    float2 a0 = make_float2(0.f, 0.f), a1 = make_float2(0.f, 0.f);             \
    float2 a2 = make_float2(0.f, 0.f), a3 = make_float2(0.f, 0.f);             \
    int2 cA = __ldg(cv + s + g);                                               \
    int2 cB = __ldg(cv + s + 4 + g);                                           \
    int2 cC = __ldg(cv + s + 8 + g);                                           \
    int2 cD = __ldg(cv + s + 12 + g);                                          \
    for (int i = s; i < e; i += 16) {                                          \
        uint4 rA = __ldg(reinterpret_cast<const uint4*>(src + (size_t)cA.x * HID) + q); \
        uint4 rB = __ldg(reinterpret_cast<const uint4*>(src + (size_t)cB.x * HID) + q); \
        uint4 rC = __ldg(reinterpret_cast<const uint4*>(src + (size_t)cC.x * HID) + q); \
        uint4 rD = __ldg(reinterpret_cast<const uint4*>(src + (size_t)cD.x * HID) + q); \
        float wA = __int_as_float(cA.y), wB = __int_as_float(cB.y);            \
        float wC = __int_as_float(cC.y), wD = __int_as_float(cD.y);            \
        cA = __ldg(cv + i + 16 + g);                                           \
        cB = __ldg(cv + i + 20 + g);                                           \
        cC = __ldg(cv + i + 24 + g);                                           \
        cD = __ldg(cv + i + 28 + g);                                           \
        ACC8(rA, wA); ACC8(rB, wB); ACC8(rC, wC); ACC8(rD, wD);                \
    }                                                                          \
    _Pragma("unroll")                                                          \
    for (int off = 8; off <= 16; off <<= 1) {                                  \
        a0.x += __shfl_xor_sync(0xFFFFFFFFu, a0.x, off);                       \
        a0.y += __shfl_xor_sync(0xFFFFFFFFu, a0.y, off);                       \
        a1.x += __shfl_xor_sync(0xFFFFFFFFu, a1.x, off);                       \
        a1.y += __shfl_xor_sync(0xFFFFFFFFu, a1.y, off);                       \
        a2.x += __shfl_xor_sync(0xFFFFFFFFu, a2.x, off);                       \
        a2.y += __shfl_xor_sync(0xFFFFFFFFu, a2.y, off);                       \
        a3.x += __shfl_xor_sync(0xFFFFFFFFu, a3.x, off);                       \
        a3.y += __shfl_xor_sync(0xFFFFFFFFu, a3.y, off);                       \
    }

// Layer-1 SpMM: epilogue relu(acc + b1), store fp16 row (lanes 0-7 store uint4)
__global__ __launch_bounds__(256) void spmm_relu_kernel(
    const int* __restrict__ rptr, const int2* __restrict__ cv,
    const __half* __restrict__ src, const float* __restrict__ b1,
    __half* __restrict__ dst, int n)
{
    int row  = (blockIdx.x * blockDim.x + threadIdx.x) >> 5;
    int lane = threadIdx.x & 31;
    if (row >= n) return;

    SPMM_BODY

    if (g == 0) {
        float4 bA = __ldg(reinterpret_cast<const float4*>(b1) + 2 * q);
        float4 bB = __ldg(reinterpret_cast<const float4*>(b1) + 2 * q + 1);
        float r0 = fmaxf(a0.x + bA.x, 0.f), r1 = fmaxf(a0.y + bA.y, 0.f);
        float r2 = fmaxf(a1.x + bA.z, 0.f), r3 = fmaxf(a1.y + bA.w, 0.f);
        float r4 = fmaxf(a2.x + bB.x, 0.f), r5 = fmaxf(a2.y + bB.y, 0.f);
        float r6 = fmaxf(a3.x + bB.z, 0.f), r7 = fmaxf(a3.y + bB.w, 0.f);
        uint4 pv = make_uint4(pack_h2(r0, r1), pack_h2(r2, r3),
                              pack_h2(r4, r5), pack_h2(r6, r7));
        reinterpret_cast<uint4*>(dst + (size_t)row * HID)[q] = pv;
    }
}

// Layer-2 SpMM fused head: relu(acc + b2) . linW, + linb -> out[row]
__global__ __launch_bounds__(256) void spmm_head_kernel(
    const int* __restrict__ rptr, const int2* __restrict__ cv,
    const __half* __restrict__ src,
    const float* __restrict__ b2, const float* __restrict__ linW,
    const float* __restrict__ linb, float* __restrict__ out, int n)
{
    int row  = (blockIdx.x * blockDim.x + threadIdx.x) >> 5;
    int lane = threadIdx.x & 31;
    if (row >= n) return;

    SPMM_BODY

    float4 bA = __ldg(reinterpret_cast<const float4*>(b2) + 2 * q);
    float4 bB = __ldg(reinterpret_cast<const float4*>(b2) + 2 * q + 1);
    float4 wAv = __ldg(reinterpret_cast<const float4*>(linW) + 2 * q);
    float4 wBv = __ldg(reinterpret_cast<const float4*>(linW) + 2 * q + 1);
    float sum = fmaxf(a0.x + bA.x, 0.f) * wAv.x + fmaxf(a0.y + bA.y, 0.f) * wAv.y
              + fmaxf(a1.x + bA.z, 0.f) * wAv.z + fmaxf(a1.y + bA.w, 0.f) * wAv.w
              + fmaxf(a2.x + bB.x, 0.f) * wBv.x + fmaxf(a2.y + bB.y, 0.f) * wBv.y
              + fmaxf(a3.x + bB.z, 0.f) * wBv.z + fmaxf(a3.y + bB.w, 0.f) * wBv.w;
    #pragma unroll
    for (int off = 1; off <= 4; off <<= 1)
        sum += __shfl_xor_sync(0xFFFFFFFFu, sum, off);
    if (lane == 0) out[row] = sum + __ldg(linb);
}

// ---------------------------------------------------------------------------
// kernel_launch
// Inputs: x, edge_row, edge_col, edge_val, W1, b1, W2, b2, lin_W, lin_b
// ---------------------------------------------------------------------------
extern "C" void kernel_launch(void* const* d_in, const int* in_sizes, int n_in,
                              void* d_out, int out_size)
{
    const float* x    = (const float*)d_in[0];
    const int*   erow = (const int*)  d_in[1];
    const int*   ecol = (const int*)  d_in[2];
    const float* eval = (const float*)d_in[3];
    const float* W1   = (const float*)d_in[4];
    const float* b1   = (const float*)d_in[5];
    const float* W2   = (const float*)d_in[6];
    const float* b2   = (const float*)d_in[7];
    const float* linW = (const float*)d_in[8];
    const float* linb = (const float*)d_in[9];
    float* out = (float*)d_out;

    const int n = in_sizes[0] / INF;
    const int E = in_sizes[1];

    __half *hA, *hB, *w1t, *w2t;
    int *deg, *rptr, *pos;
    int2 *cv;
    cudaGetSymbolAddress((void**)&hA,   g_hA);
    cudaGetSymbolAddress((void**)&hB,   g_hB);
    cudaGetSymbolAddress((void**)&w1t,  g_w1t);
    cudaGetSymbolAddress((void**)&w2t,  g_w2t);
    cudaGetSymbolAddress((void**)&deg,  g_deg);
    cudaGetSymbolAddress((void**)&rptr, g_rptr);
    cudaGetSymbolAddress((void**)&pos,  g_pos);
    cudaGetSymbolAddress((void**)&cv,   g_cv);

    static bool init_done = false;
    static cudaStream_t side = nullptr;
    static cudaEvent_t evFork = nullptr, evJoin = nullptr;
    if (!init_done) {
        cudaFuncSetAttribute(gemm_in_tc,
                             cudaFuncAttributeMaxDynamicSharedMemorySize, 65536);
        cudaStreamCreateWithFlags(&side, cudaStreamNonBlocking);
        cudaEventCreateWithFlags(&evFork, cudaEventDisableTiming);
        cudaEventCreateWithFlags(&evJoin, cudaEventDisableTiming);
        init_done = true;
    }

    const int nb         = (n + 1023) / 1024;     // scan blocks (<=128)
    const int tc_grid    = (n + 127) / 128;       // 128-row tiles
    const int spmm_grid  = (n * 32 + 255) / 256;  // warp per row
    const int smem1      = (128 * XS1 + 64 * XS1) * (int)sizeof(__half);

    // --- Fork: CSR build on side stream, overlapped with main-stream GEMM1 ---
    cudaEventRecord(evFork, 0);
    cudaStreamWaitEvent(side, evFork, 0);
    hist_kernel<<<2048, 256, 0, side>>>(erow, deg, pos, E);
    scan_kernel<<<nb, 256, 0, side>>>(deg, rptr, cv, n, nb);
    scatter_kernel<<<2048, 256, 0, side>>>(erow, ecol, eval, pos, rptr, cv, deg, n, E);
    cudaEventRecord(evJoin, side);

    // --- Main stream: weight convert + GEMM1 (tensor cores) ---
    wconv_kernel<<<48, 256>>>(W1, W2, w1t, w2t);
    gemm_in_tc<<<tc_grid, 256, smem1>>>(x, w1t, hA, n);

    // --- Join, then layer-1 SpMM (+bias1+relu): hB = relu(A@hA + b1) ---
    cudaStreamWaitEvent(0, evJoin, 0);
    spmm_relu_kernel<<<spmm_grid, 256>>>(rptr, cv, hA, b1, hB, n);

    // --- Layer 2: hA = hB @ W2 ; out = head(A@hA) ---
    gemm_hid_tc<<<tc_grid, 256>>>(hB, w2t, hA, n);
    spmm_head_kernel<<<spmm_grid, 256>>>(rptr, cv, hA, b2, linW, linb, out, n);
}

// round 17
// speedup vs baseline: 1.0772x; 1.0772x over previous
// R16 = exact resubmission of the R13 champion (217.2 us measured).
// R15 falsified the padded/v4 SpMM theory (SpMM is L2-byte-bound; padding
// adds bytes). All roofline-bound components locked at their best-measured
// configurations.
#include <cuda_runtime.h>
#include <cuda_fp16.h>
#include <cstdint>

// Problem constants (shapes fixed by the reference)
#define MAXN    100000
#define MAXE    3400000
#define INF     128
#define HID     64
#define MAXCV   (MAXE + 256)

// Scratch (device globals per allocation rules)
__device__ __half g_hA[(size_t)MAXN * HID];    // feature table A (12.8 MB)
__device__ __half g_hB[(size_t)MAXN * HID];    // feature table B (12.8 MB)
__device__ __half g_w1t[64 * 128];             // W1^T (n-major) fp16
__device__ __half g_w2t[64 * 64];              // W2^T (n-major) fp16
__device__ int   g_deg[MAXN];                  // reset by scatter each replay
__device__ int   g_rptr[MAXN + 1];
__device__ int   g_pos[MAXE];                  // per-edge within-row position
__device__ int2  g_cv[MAXCV];                  // (col, val-bits) sorted by row
__device__ int   g_flag[128];                  // lookback flags (0/1/2)
__device__ int   g_agg[128];
__device__ int   g_pref[128];

__device__ __forceinline__ uint32_t pack_h2(float a, float b) {
    __half2 h = __floats2half2_rn(a, b);
    return *reinterpret_cast<uint32_t*>(&h);
}

// m16n8k16 fp16 MMA, fp32 accum, in-place C
__device__ __forceinline__ void mma16816(float* c,
    uint32_t a0, uint32_t a1, uint32_t a2, uint32_t a3,
    uint32_t b0, uint32_t b1)
{
    asm volatile(
        "mma.sync.aligned.m16n8k16.row.col.f32.f16.f16.f32 "
        "{%0,%1,%2,%3}, {%4,%5,%6,%7}, {%8,%9}, {%0,%1,%2,%3};\n"
        : "+f"(c[0]), "+f"(c[1]), "+f"(c[2]), "+f"(c[3])
        : "r"(a0), "r"(a1), "r"(a2), "r"(a3), "r"(b0), "r"(b1));
}

// ---------------------------------------------------------------------------
// Weight transpose + fp16 convert: Wt[n][k] = W[k][n]
// ---------------------------------------------------------------------------
__global__ void wconv_kernel(const float* __restrict__ W1,
                             const float* __restrict__ W2,
                             __half* __restrict__ Wt1, __half* __restrict__ Wt2)
{
    int i = blockIdx.x * blockDim.x + threadIdx.x;
    if (i < 64 * 128) {
        int nn = i >> 7, k = i & 127;
        Wt1[i] = __float2half(W1[k * 64 + nn]);
    }
    int j = i - 64 * 128;
    if (j >= 0 && j < 64 * 64) {
        int nn = j >> 6, k = j & 63;
        Wt2[j] = __float2half(W2[k * 64 + nn]);
    }
}

// ---------------------------------------------------------------------------
// Build: hist (atomic returns = within-row position, ILP4) ->
//        scan (single decoupled-lookback) -> atomic-free scatter
// ---------------------------------------------------------------------------
__global__ void hist_kernel(const int* __restrict__ erow, int* __restrict__ deg,
                            int* __restrict__ pos, int E)
{
    int t = blockIdx.x * blockDim.x + threadIdx.x;
    int stride4 = gridDim.x * blockDim.x * 4;
    for (int i = t * 4; i + 4 <= E; i += stride4) {
        int4 r = __ldg(reinterpret_cast<const int4*>(erow + i));
        int p0 = atomicAdd(deg + r.x, 1);
        int p1 = atomicAdd(deg + r.y, 1);
        int p2 = atomicAdd(deg + r.z, 1);
        int p3 = atomicAdd(deg + r.w, 1);
        *reinterpret_cast<int4*>(pos + i) = make_int4(p0, p1, p2, p3);
    }
    if (t == 0)
        for (int j = E & ~3; j < E; j++)
            pos[j] = atomicAdd(deg + __ldg(erow + j), 1);
}

// Exclusive scan of raw degrees, decoupled lookback (nb <= 128 co-resident
// blocks). Flags zero on entry (static init; scatter resets each replay).
__global__ __launch_bounds__(256) void scan_kernel(
    const int* __restrict__ deg, int* __restrict__ rptr, int n, int nb)
{
    __shared__ int sh[256];
    __shared__ int sh_base;
    const int tid = threadIdx.x;
    const int bid = blockIdx.x;

    int base = bid * 1024 + tid * 4;
    int v[4]; int s4 = 0;
    #pragma unroll
    for (int j = 0; j < 4; j++) {
        v[j] = (base + j < n) ? deg[base + j] : 0;
        s4 += v[j];
    }
    sh[tid] = s4; __syncthreads();
    #pragma unroll
    for (int off = 1; off < 256; off <<= 1) {
        int y = (tid >= off) ? sh[tid - off] : 0;
        __syncthreads();
        sh[tid] += y;
        __syncthreads();
    }
    int total = sh[255];

    if (tid == 0) {
        int b;
        if (bid == 0) {
            g_pref[0] = total;
            __threadfence();
            atomicExch(&g_flag[0], 2);
            b = 0;
        } else {
            g_agg[bid] = total;
            __threadfence();
            atomicExch(&g_flag[bid], 1);
            int sum = 0;
            for (int j = bid - 1; ; ) {
                int f;
                do { f = atomicAdd(&g_flag[j], 0); } while (f == 0);
                if (f == 2) { sum += atomicAdd(&g_pref[j], 0); break; }
                sum += atomicAdd(&g_agg[j], 0);
                j--;
            }
            g_pref[bid] = sum + total;
            __threadfence();
            atomicExch(&g_flag[bid], 2);
            b = sum;
        }
        sh_base = b;
        if (bid == nb - 1) rptr[n] = b + total;
    }
    __syncthreads();

    int excl = sh[tid] - s4 + sh_base;
    #pragma unroll
    for (int j = 0; j < 4; j++) {
        if (base + j < n) rptr[base + j] = excl;
        excl += v[j];
    }
}

// Atomic-free placement: cv[rptr[r] + pos[i]] = (col, val). 4-edge ILP.
// Resets deg/flags for the next graph replay.
__global__ void scatter_kernel(
    const int* __restrict__ erow, const int* __restrict__ ecol,
    const float* __restrict__ eval, const int* __restrict__ pos,
    const int* __restrict__ rptr, int2* __restrict__ cv,
    int* __restrict__ deg, int n, int E)
{
    int t = blockIdx.x * blockDim.x + threadIdx.x;
    int stride = gridDim.x * blockDim.x;
    int stride4 = stride * 4;
    for (int i = t * 4; i + 4 <= E; i += stride4) {
        int4   r = __ldg(reinterpret_cast<const int4*>(erow + i));
        int4   c = __ldg(reinterpret_cast<const int4*>(ecol + i));
        float4 v = __ldg(reinterpret_cast<const float4*>(eval + i));
        int4   p = __ldg(reinterpret_cast<const int4*>(pos + i));
        int b0 = __ldg(rptr + r.x);
        int b1 = __ldg(rptr + r.y);
        int b2 = __ldg(rptr + r.z);
        int b3 = __ldg(rptr + r.w);
        cv[b0 + p.x] = make_int2(c.x, __float_as_int(v.x));
        cv[b1 + p.y] = make_int2(c.y, __float_as_int(v.y));
        cv[b2 + p.z] = make_int2(c.z, __float_as_int(v.z));
        cv[b3 + p.w] = make_int2(c.w, __float_as_int(v.w));
    }
    if (t == 0) {
        for (int j = E & ~3; j < E; j++) {
            int r = __ldg(erow + j);
            cv[__ldg(rptr + r) + pos[j]] =
                make_int2(__ldg(ecol + j), __float_as_int(__ldg(eval + j)));
        }
    }
    for (int i = t; i < n; i += stride) deg[i] = 0;
    if (t < 128) g_flag[t] = 0;
}

// ---------------------------------------------------------------------------
// GEMM1 (tensor core): H[n,64] fp16 = X[n,128] fp32 @ W1[128,64]
// ---------------------------------------------------------------------------
#define XS1 136
__global__ __launch_bounds__(256) void gemm_in_tc(
    const float* __restrict__ X, const __half* __restrict__ Wt,
    __half* __restrict__ H, int n)
{
    extern __shared__ __half sm1[];
    __half* xs = sm1;               // [128][136]
    __half* ws = sm1 + 128 * XS1;   // [64][136]

    const int tid  = threadIdx.x;
    const int row0 = blockIdx.x * 128;

    for (int idx = tid; idx < 64 * 16; idx += 256) {
        int r = idx >> 4, c = idx & 15;
        uint4 v = *reinterpret_cast<const uint4*>(Wt + r * 128 + c * 8);
        *reinterpret_cast<uint4*>(ws + r * XS1 + c * 8) = v;
    }
    for (int idx = tid; idx < 128 * 16; idx += 256) {
        int r = idx >> 4, c = idx & 15;
        int gr = row0 + r;
        uint4 o = make_uint4(0u, 0u, 0u, 0u);
        if (gr < n) {
            const float4* p = reinterpret_cast<const float4*>(X + (size_t)gr * INF + c * 8);
            float4 f0 = __ldg(p);
            float4 f1 = __ldg(p + 1);
            o.x = pack_h2(f0.x, f0.y); o.y = pack_h2(f0.z, f0.w);
            o.z = pack_h2(f1.x, f1.y); o.w = pack_h2(f1.z, f1.w);
        }
        *reinterpret_cast<uint4*>(xs + r * XS1 + c * 8) = o;
    }
    __syncthreads();

    const int warp = tid >> 5, lane = tid & 31;
    const int g = lane >> 2, tg = lane & 3;
    const int m0 = warp * 16;

    float acc[8][4];
    #pragma unroll
    for (int i = 0; i < 8; i++)
        #pragma unroll
        for (int j = 0; j < 4; j++) acc[i][j] = 0.f;

    const __half* xb = xs + (m0 + g) * XS1 + 2 * tg;
    const __half* wb = ws + g * XS1 + 2 * tg;

    #pragma unroll
    for (int kb = 0; kb < 128; kb += 16) {
        uint32_t a0 = *reinterpret_cast<const uint32_t*>(xb + kb);
        uint32_t a1 = *reinterpret_cast<const uint32_t*>(xb + kb + 8 * XS1);
        uint32_t a2 = *reinterpret_cast<const uint32_t*>(xb + kb + 8);
        uint32_t a3 = *reinterpret_cast<const uint32_t*>(xb + kb + 8 * XS1 + 8);
        #pragma unroll
        for (int nf = 0; nf < 8; nf++) {
            uint32_t b0 = *reinterpret_cast<const uint32_t*>(wb + nf * 8 * XS1 + kb);
            uint32_t b1 = *reinterpret_cast<const uint32_t*>(wb + nf * 8 * XS1 + kb + 8);
            mma16816(acc[nf], a0, a1, a2, a3, b0, b1);
        }
    }

    const int r1 = row0 + m0 + g, r2 = r1 + 8;
    #pragma unroll
    for (int nf = 0; nf < 8; nf++) {
        int col = nf * 8 + 2 * tg;
        if (r1 < n)
            *reinterpret_cast<uint32_t*>(H + (size_t)r1 * HID + col) = pack_h2(acc[nf][0], acc[nf][1]);
        if (r2 < n)
            *reinterpret_cast<uint32_t*>(H + (size_t)r2 * HID + col) = pack_h2(acc[nf][2], acc[nf][3]);
    }
}

// ---------------------------------------------------------------------------
// GEMM2 (tensor core): H2[n,64] fp16 = H1[n,64] fp16 @ W2[64,64]
// ---------------------------------------------------------------------------
#define XS2 72
__global__ __launch_bounds__(256) void gemm_hid_tc(
    const __half* __restrict__ Hin, const __half* __restrict__ Wt,
    __half* __restrict__ Hout, int n)
{
    __shared__ __half xs[128 * XS2];
    __shared__ __half ws[64 * XS2];

    const int tid  = threadIdx.x;
    const int row0 = blockIdx.x * 128;

    for (int idx = tid; idx < 64 * 8; idx += 256) {
        int r = idx >> 3, c = idx & 7;
        uint4 v = *reinterpret_cast<const uint4*>(Wt + r * 64 + c * 8);
        *reinterpret_cast<uint4*>(ws + r * XS2 + c * 8) = v;
    }
    for (int idx = tid; idx < 128 * 8; idx += 256) {
        int r = idx >> 3, c = idx & 7;
        int gr = row0 + r;
        uint4 v = make_uint4(0u, 0u, 0u, 0u);
        if (gr < n)
            v = __ldg(reinterpret_cast<const uint4*>(Hin + (size_t)gr * HID + c * 8));
        *reinterpret_cast<uint4*>(xs + r * XS2 + c * 8) = v;
    }
    __syncthreads();

    const int warp = tid >> 5, lane = tid & 31;
    const int g = lane >> 2, tg = lane & 3;
    const int m0 = warp * 16;

    float acc[8][4];
    #pragma unroll
    for (int i = 0; i < 8; i++)
        #pragma unroll
        for (int j = 0; j < 4; j++) acc[i][j] = 0.f;

    const __half* xb = xs + (m0 + g) * XS2 + 2 * tg;
    const __half* wb = ws + g * XS2 + 2 * tg;

    #pragma unroll
    for (int kb = 0; kb < 64; kb += 16) {
        uint32_t a0 = *reinterpret_cast<const uint32_t*>(xb + kb);
        uint32_t a1 = *reinterpret_cast<const uint32_t*>(xb + kb + 8 * XS2);
        uint32_t a2 = *reinterpret_cast<const uint32_t*>(xb + kb + 8);
        uint32_t a3 = *reinterpret_cast<const uint32_t*>(xb + kb + 8 * XS2 + 8);
        #pragma unroll
        for (int nf = 0; nf < 8; nf++) {
            uint32_t b0 = *reinterpret_cast<const uint32_t*>(wb + nf * 8 * XS2 + kb);
            uint32_t b1 = *reinterpret_cast<const uint32_t*>(wb + nf * 8 * XS2 + kb + 8);
            mma16816(acc[nf], a0, a1, a2, a3, b0, b1);
        }
    }

    const int r1 = row0 + m0 + g, r2 = r1 + 8;
    #pragma unroll
    for (int nf = 0; nf < 8; nf++) {
        int col = nf * 8 + 2 * tg;
        if (r1 < n)
            *reinterpret_cast<uint32_t*>(Hout + (size_t)r1 * HID + col) = pack_h2(acc[nf][0], acc[nf][1]);
        if (r2 < n)
            *reinterpret_cast<uint32_t*>(Hout + (size_t)r2 * HID + col) = pack_h2(acc[nf][2], acc[nf][3]);
    }
}

// ---------------------------------------------------------------------------
// SpMM core v2 (champion): warp per dest row; 8 edges/iter, unroll 2,
// predicated tails. At the L2 random-line roofline (~6.5TB/s).
// ---------------------------------------------------------------------------
#define SPMM_BODY                                                              \
    int g = lane >> 3;                                                         \
    int q = lane & 7;                                                          \
    int s = __ldg(rptr + row);                                                 \
    int e = __ldg(rptr + row + 1);                                             \
    float2 a0 = make_float2(0.f, 0.f), a1 = make_float2(0.f, 0.f);             \
    float2 a2 = make_float2(0.f, 0.f), a3 = make_float2(0.f, 0.f);             \
    _Pragma("unroll 2")                                                        \
    for (int i = s; i < e; i += 8) {                                           \
        int  iA = i + g,      iB = i + 4 + g;                                  \
        bool vA = iA < e,     vB = iB < e;                                     \
        int2 cA = __ldg(cv + (vA ? iA : s));                                   \
        int2 cB = __ldg(cv + (vB ? iB : s));                                   \
        float wA = vA ? __int_as_float(cA.y) : 0.f;                            \
        float wB = vB ? __int_as_float(cB.y) : 0.f;                            \
        uint4 rA = __ldg(reinterpret_cast<const uint4*>(src + (size_t)cA.x * HID) + q); \
        uint4 rB = __ldg(reinterpret_cast<const uint4*>(src + (size_t)cB.x * HID) + q); \
        float2 f;                                                              \
        f = __half22float2(*reinterpret_cast<__half2*>(&rA.x));                \
        a0.x = fmaf(wA, f.x, a0.x); a0.y = fmaf(wA, f.y, a0.y);                \
        f = __half22float2(*reinterpret_cast<__half2*>(&rA.y));                \
        a1.x = fmaf(wA, f.x, a1.x); a1.y = fmaf(wA, f.y, a1.y);                \
        f = __half22float2(*reinterpret_cast<__half2*>(&rA.z));                \
        a2.x = fmaf(wA, f.x, a2.x); a2.y = fmaf(wA, f.y, a2.y);                \
        f = __half22float2(*reinterpret_cast<__half2*>(&rA.w));                \
        a3.x = fmaf(wA, f.x, a3.x); a3.y = fmaf(wA, f.y, a3.y);                \
        f = __half22float2(*reinterpret_cast<__half2*>(&rB.x));                \
        a0.x = fmaf(wB, f.x, a0.x); a0.y = fmaf(wB, f.y, a0.y);                \
        f = __half22float2(*reinterpret_cast<__half2*>(&rB.y));                \
        a1.x = fmaf(wB, f.x, a1.x); a1.y = fmaf(wB, f.y, a1.y);                \
        f = __half22float2(*reinterpret_cast<__half2*>(&rB.z));                \
        a2.x = fmaf(wB, f.x, a2.x); a2.y = fmaf(wB, f.y, a2.y);                \
        f = __half22float2(*reinterpret_cast<__half2*>(&rB.w));                \
        a3.x = fmaf(wB, f.x, a3.x); a3.y = fmaf(wB, f.y, a3.y);                \
    }                                                                          \
    _Pragma("unroll")                                                          \
    for (int off = 8; off <= 16; off <<= 1) {                                  \
        a0.x += __shfl_xor_sync(0xFFFFFFFFu, a0.x, off);                       \
        a0.y += __shfl_xor_sync(0xFFFFFFFFu, a0.y, off);                       \
        a1.x += __shfl_xor_sync(0xFFFFFFFFu, a1.x, off);                       \
        a1.y += __shfl_xor_sync(0xFFFFFFFFu, a1.y, off);                       \
        a2.x += __shfl_xor_sync(0xFFFFFFFFu, a2.x, off);                       \
        a2.y += __shfl_xor_sync(0xFFFFFFFFu, a2.y, off);                       \
        a3.x += __shfl_xor_sync(0xFFFFFFFFu, a3.x, off);                       \
        a3.y += __shfl_xor_sync(0xFFFFFFFFu, a3.y, off);                       \
    }

// Layer-1 SpMM: epilogue relu(acc + b1), store fp16 row (lanes 0-7 store uint4)
__global__ __launch_bounds__(256) void spmm_relu_kernel(
    const int* __restrict__ rptr, const int2* __restrict__ cv,
    const __half* __restrict__ src, const float* __restrict__ b1,
    __half* __restrict__ dst, int n)
{
    int row  = (blockIdx.x * blockDim.x + threadIdx.x) >> 5;
    int lane = threadIdx.x & 31;
    if (row >= n) return;

    SPMM_BODY

    if (g == 0) {
        float4 bA = __ldg(reinterpret_cast<const float4*>(b1) + 2 * q);
        float4 bB = __ldg(reinterpret_cast<const float4*>(b1) + 2 * q + 1);
        float r0 = fmaxf(a0.x + bA.x, 0.f), r1 = fmaxf(a0.y + bA.y, 0.f);
        float r2 = fmaxf(a1.x + bA.z, 0.f), r3 = fmaxf(a1.y + bA.w, 0.f);
        float r4 = fmaxf(a2.x + bB.x, 0.f), r5 = fmaxf(a2.y + bB.y, 0.f);
        float r6 = fmaxf(a3.x + bB.z, 0.f), r7 = fmaxf(a3.y + bB.w, 0.f);
        uint4 pv = make_uint4(pack_h2(r0, r1), pack_h2(r2, r3),
                              pack_h2(r4, r5), pack_h2(r6, r7));
        reinterpret_cast<uint4*>(dst + (size_t)row * HID)[q] = pv;
    }
}

// Layer-2 SpMM fused head: relu(acc + b2) . linW, + linb -> out[row]
__global__ __launch_bounds__(256) void spmm_head_kernel(
    const int* __restrict__ rptr, const int2* __restrict__ cv,
    const __half* __restrict__ src,
    const float* __restrict__ b2, const float* __restrict__ linW,
    const float* __restrict__ linb, float* __restrict__ out, int n)
{
    int row  = (blockIdx.x * blockDim.x + threadIdx.x) >> 5;
    int lane = threadIdx.x & 31;
    if (row >= n) return;

    SPMM_BODY

    float4 bA = __ldg(reinterpret_cast<const float4*>(b2) + 2 * q);
    float4 bB = __ldg(reinterpret_cast<const float4*>(b2) + 2 * q + 1);
    float4 wAv = __ldg(reinterpret_cast<const float4*>(linW) + 2 * q);
    float4 wBv = __ldg(reinterpret_cast<const float4*>(linW) + 2 * q + 1);
    float sum = fmaxf(a0.x + bA.x, 0.f) * wAv.x + fmaxf(a0.y + bA.y, 0.f) * wAv.y
              + fmaxf(a1.x + bA.z, 0.f) * wAv.z + fmaxf(a1.y + bA.w, 0.f) * wAv.w
              + fmaxf(a2.x + bB.x, 0.f) * wBv.x + fmaxf(a2.y + bB.y, 0.f) * wBv.y
              + fmaxf(a3.x + bB.z, 0.f) * wBv.z + fmaxf(a3.y + bB.w, 0.f) * wBv.w;
    #pragma unroll
    for (int off = 1; off <= 4; off <<= 1)
        sum += __shfl_xor_sync(0xFFFFFFFFu, sum, off);
    if (lane == 0) out[row] = sum + __ldg(linb);
}

// ---------------------------------------------------------------------------
// kernel_launch
// Inputs: x, edge_row, edge_col, edge_val, W1, b1, W2, b2, lin_W, lin_b
// ---------------------------------------------------------------------------
extern "C" void kernel_launch(void* const* d_in, const int* in_sizes, int n_in,
                              void* d_out, int out_size)
{
    const float* x    = (const float*)d_in[0];
    const int*   erow = (const int*)  d_in[1];
    const int*   ecol = (const int*)  d_in[2];
    const float* eval = (const float*)d_in[3];
    const float* W1   = (const float*)d_in[4];
    const float* b1   = (const float*)d_in[5];
    const float* W2   = (const float*)d_in[6];
    const float* b2   = (const float*)d_in[7];
    const float* linW = (const float*)d_in[8];
    const float* linb = (const float*)d_in[9];
    float* out = (float*)d_out;

    const int n = in_sizes[0] / INF;
    const int E = in_sizes[1];

    __half *hA, *hB, *w1t, *w2t;
    int *deg, *rptr, *pos;
    int2 *cv;
    cudaGetSymbolAddress((void**)&hA,   g_hA);
    cudaGetSymbolAddress((void**)&hB,   g_hB);
    cudaGetSymbolAddress((void**)&w1t,  g_w1t);
    cudaGetSymbolAddress((void**)&w2t,  g_w2t);
    cudaGetSymbolAddress((void**)&deg,  g_deg);
    cudaGetSymbolAddress((void**)&rptr, g_rptr);
    cudaGetSymbolAddress((void**)&pos,  g_pos);
    cudaGetSymbolAddress((void**)&cv,   g_cv);

    static bool init_done = false;
    static cudaStream_t side = nullptr;
    static cudaEvent_t evFork = nullptr, evJoin = nullptr;
    if (!init_done) {
        cudaFuncSetAttribute(gemm_in_tc,
                             cudaFuncAttributeMaxDynamicSharedMemorySize, 65536);
        cudaStreamCreateWithFlags(&side, cudaStreamNonBlocking);
        cudaEventCreateWithFlags(&evFork, cudaEventDisableTiming);
        cudaEventCreateWithFlags(&evJoin, cudaEventDisableTiming);
        init_done = true;
    }

    const int nb         = (n + 1023) / 1024;     // scan blocks (<=128)
    const int tc_grid    = (n + 127) / 128;       // 128-row tiles
    const int spmm_grid  = (n * 32 + 255) / 256;  // warp per row
    const int smem1      = (128 * XS1 + 64 * XS1) * (int)sizeof(__half);

    // --- Fork: CSR build on side stream, overlapped with main-stream GEMM1 ---
    cudaEventRecord(evFork, 0);
    cudaStreamWaitEvent(side, evFork, 0);
    hist_kernel<<<2048, 256, 0, side>>>(erow, deg, pos, E);
    scan_kernel<<<nb, 256, 0, side>>>(deg, rptr, n, nb);
    scatter_kernel<<<2048, 256, 0, side>>>(erow, ecol, eval, pos, rptr, cv, deg, n, E);
    cudaEventRecord(evJoin, side);

    // --- Main stream: weight convert + GEMM1 (tensor cores) ---
    wconv_kernel<<<48, 256>>>(W1, W2, w1t, w2t);
    gemm_in_tc<<<tc_grid, 256, smem1>>>(x, w1t, hA, n);

    // --- Join, then layer-1 SpMM (+bias1+relu): hB = relu(A@hA + b1) ---
    cudaStreamWaitEvent(0, evJoin, 0);
    spmm_relu_kernel<<<spmm_grid, 256>>>(rptr, cv, hA, b1, hB, n);

    // --- Layer 2: hA = hB @ W2 ; out = head(A@hA) ---
    gemm_hid_tc<<<tc_grid, 256>>>(hB, w2t, hA, n);
    spmm_head_kernel<<<spmm_grid, 256>>>(rptr, cv, hA, b2, linW, linb, out, n);
}